// round 14
// baseline (speedup 1.0000x reference)
#include <cuda_runtime.h>
#include <cuda_bf16.h>
#include <cuda_fp16.h>
#include <cstdint>

#define NN   50000
#define EE   800000
#define DH   128

// ---------------- device scratch ----------
__device__ int    g_is64;
__device__ int    g_src[EE];
__device__ int    g_dst[EE];
__device__ int    g_cnt[NN];
__device__ int    g_off[NN];
__device__ int    g_pos[NN];
__device__ float  g_dinv[NN];
__device__ int2   g_edge[EE];                 // {src, norm bits} per CSR slot
__device__ __half g_xwh[NN * DH];             // GEMM output, fp16 gather payload
__device__ unsigned short g_ah[NN * DH];      // activations, bf16 hi
__device__ unsigned short g_al[NN * DH];      // activations, bf16 lo
__device__ unsigned short g_wh[3 * DH * DH];  // W^T hi per layer, [l][n][k]
__device__ unsigned short g_wl[3 * DH * DH];  // W^T lo per layer

__device__ __forceinline__ uint32_t bsplit_hi(float x, float& rem) {
    __nv_bfloat16 hb = __float2bfloat16_rn(x);
    rem = x - __bfloat162float(hb);
    return (uint32_t)__bfloat16_as_ushort(hb);
}

__device__ __forceinline__ uint32_t smem_u32(const void* p) {
    uint32_t a;
    asm("{ .reg .u64 t; cvta.to.shared.u64 t, %1; cvt.u32.u64 %0, t; }" : "=r"(a) : "l"(p));
    return a;
}
__device__ __forceinline__ void cp16(uint32_t dst, const void* src) {
    asm volatile("cp.async.ca.shared.global [%0], [%1], 16;"
                 :: "r"(dst), "l"(__cvta_generic_to_global(src)));
}
__device__ __forceinline__ void cp_commit() {
    asm volatile("cp.async.commit_group;");
}
template <int N>
__device__ __forceinline__ void cp_wait() {
    asm volatile("cp.async.wait_group %0;" :: "n"(N));
}

// ---------------- x -> bf16 hi/lo split (one-shot) ----------------
__global__ void k_splitx(const float* __restrict__ x) {
    int i = blockIdx.x * blockDim.x + threadIdx.x;   // one float4 per thread
    if (i >= NN * DH / 4) return;
    float4 v = ((const float4*)x)[i];
    float rx, ry, rz, rw, z;
    uint32_t hx = bsplit_hi(v.x, rx), hy = bsplit_hi(v.y, ry);
    uint32_t hz = bsplit_hi(v.z, rz), hw = bsplit_hi(v.w, rw);
    uint32_t lx = bsplit_hi(rx, z), ly = bsplit_hi(ry, z);
    uint32_t lz = bsplit_hi(rz, z), lw = bsplit_hi(rw, z);
    ((uint2*)g_ah)[i] = make_uint2(hx | (hy << 16), hz | (hw << 16));
    ((uint2*)g_al)[i] = make_uint2(lx | (ly << 16), lz | (lw << 16));
}

// ---------------- W^T + bf16 split for all 3 layers -------------------
__global__ void k_wprep3(const float* __restrict__ W1,
                         const float* __restrict__ W2,
                         const float* __restrict__ W3) {
    int n = blockIdx.x, l = blockIdx.y, k = threadIdx.x;
    const float* W = (l == 0) ? W1 : (l == 1) ? W2 : W3;
    float v = W[k * DH + n];
    float r;
    uint32_t h = bsplit_hi(v, r);
    uint32_t lo = bsplit_hi(r, v);
    g_wh[l * DH * DH + n * DH + k] = (unsigned short)h;
    g_wl[l * DH * DH + n * DH + k] = (unsigned short)lo;
}

// ---------------- zero + dtype detection (fused) ----------------
__global__ void k_dz(const void* ei) {
    int i = blockIdx.x * blockDim.x + threadIdx.x;
    if (i < NN) { g_cnt[i] = 0; g_pos[i] = 0; }
    if (i == 0) {
        const unsigned* p = (const unsigned*)ei;
        int is64 = 1;
        for (int q = 0; q < 64; q++)
            if (p[2 * q + 1] != 0u) { is64 = 0; break; }
        g_is64 = is64;
    }
}

__global__ void k_convert_count(const void* ei) {
    int e = blockIdx.x * blockDim.x + threadIdx.x;
    if (e >= EE) return;
    int s, d;
    if (g_is64) {
        const long long* p = (const long long*)ei;
        s = (int)p[e]; d = (int)p[EE + e];
    } else {
        const int* p = (const int*)ei;
        s = p[e]; d = p[EE + e];
    }
    g_src[e] = s; g_dst[e] = d;
    atomicAdd(&g_cnt[d], 1);
}

// single-block exclusive scan (shfl-based) + dinv (fused)
__global__ void k_scan() {
    __shared__ int wsum[32];
    const int C = (NN + 1023) / 1024;
    int t = threadIdx.x, lane = t & 31, wid = t >> 5;
    int beg = t * C;
    int end = min(beg + C, NN);
    int s = 0;
    for (int i = beg; i < end; i++) s += g_cnt[i];
    int v = s;
    #pragma unroll
    for (int d = 1; d < 32; d <<= 1) {
        int u = __shfl_up_sync(0xFFFFFFFFu, v, d);
        if (lane >= d) v += u;
    }
    if (lane == 31) wsum[wid] = v;
    __syncthreads();
    if (wid == 0) {
        int w = wsum[lane];
        #pragma unroll
        for (int d = 1; d < 32; d <<= 1) {
            int u = __shfl_up_sync(0xFFFFFFFFu, w, d);
            if (lane >= d) w += u;
        }
        wsum[lane] = w;
    }
    __syncthreads();
    int run = v - s + (wid ? wsum[wid - 1] : 0);
    for (int i = beg; i < end; i++) {
        int c = g_cnt[i];
        g_off[i] = run;
        g_dinv[i] = rsqrtf((float)c + 1.0f);
        run += c;
    }
}

__global__ void k_scatter() {
    int e = blockIdx.x * blockDim.x + threadIdx.x;
    if (e >= EE) return;
    int s = g_src[e];
    int d = g_dst[e];
    int p = g_off[d] + atomicAdd(&g_pos[d], 1);
    g_edge[p] = make_int2(s, __float_as_int(g_dinv[s] * g_dinv[d]));
}

// ---------------- bf16x3 mma GEMM: g_xwh = fp16( A @ W ) ----------------
// CTA tile 128x128; K in 4 chunks of 32, double-buffered cp.async pipeline.
// 80KB SMEM -> 2 CTAs/SM. Operands pre-split bf16; copies are cp.async.
#define ROWB3  80          // 32 halves * 2B + 16 pad
#define CHUNKB (128 * ROWB3)
#define SM3_AH 0
#define SM3_AL (SM3_AH + 2 * CHUNKB)
#define SM3_BH (SM3_AL + 2 * CHUNKB)
#define SM3_BL (SM3_BH + 2 * CHUNKB)
#define SM3_TOTAL (SM3_BL + 2 * CHUNKB)   // 81920 B

__device__ __forceinline__ void mma_bf16(float* d, uint32_t a0, uint32_t a1,
                                         uint32_t a2, uint32_t a3,
                                         uint32_t b0, uint32_t b1) {
    asm volatile(
        "mma.sync.aligned.m16n8k16.row.col.f32.bf16.bf16.f32 "
        "{%0,%1,%2,%3}, {%4,%5,%6,%7}, {%8,%9}, {%0,%1,%2,%3};"
        : "+f"(d[0]), "+f"(d[1]), "+f"(d[2]), "+f"(d[3])
        : "r"(a0), "r"(a1), "r"(a2), "r"(a3), "r"(b0), "r"(b1));
}

__global__ __launch_bounds__(256, 2) void k_gemm_mma(int layer) {
    extern __shared__ char sm[];
    uint32_t smb = smem_u32(sm);
    int tid  = threadIdx.x;
    int wid  = tid >> 5;
    int lane = tid & 31;
    int r0   = blockIdx.x * 128;

    const unsigned short* WH = g_wh + layer * DH * DH;
    const unsigned short* WL = g_wl + layer * DH * DH;

    int cr = tid >> 1;           // copy row (0..127)
    int hf = tid & 1;            // half of 32-elem chunk (16 halves = 32B)
    int arow = min(r0 + cr, NN - 1);

    // prefetch chunk kc into buffer kc&1 (8 x cp16 per thread)
    auto prefetch = [&](int kc) {
        int buf = kc & 1;
        size_t aoff = (size_t)arow * DH + kc * 32 + hf * 16;
        size_t boff = (size_t)cr   * DH + kc * 32 + hf * 16;
        uint32_t dA = smb + SM3_AH + buf * CHUNKB + cr * ROWB3 + hf * 32;
        uint32_t dL = smb + SM3_AL + buf * CHUNKB + cr * ROWB3 + hf * 32;
        uint32_t dB = smb + SM3_BH + buf * CHUNKB + cr * ROWB3 + hf * 32;
        uint32_t dC = smb + SM3_BL + buf * CHUNKB + cr * ROWB3 + hf * 32;
        cp16(dA,      g_ah + aoff);
        cp16(dA + 16, g_ah + aoff + 8);
        cp16(dL,      g_al + aoff);
        cp16(dL + 16, g_al + aoff + 8);
        cp16(dB,      WH + boff);
        cp16(dB + 16, WH + boff + 8);
        cp16(dC,      WL + boff);
        cp16(dC + 16, WL + boff + 8);
        cp_commit();
    };

    // warp grid: wm = wid & 1 (2 x 64 rows), wn = wid >> 1 (4 x 32 cols)
    int wm = (wid & 1) * 64;
    int wn = (wid >> 1) * 32;
    int g  = lane >> 2;      // 0..7
    int t  = lane & 3;       // 0..3

    float acc[4][4][4];
    #pragma unroll
    for (int mt = 0; mt < 4; mt++)
        #pragma unroll
        for (int nt = 0; nt < 4; nt++)
            #pragma unroll
            for (int q = 0; q < 4; q++) acc[mt][nt][q] = 0.0f;

    prefetch(0);

    #pragma unroll
    for (int kc = 0; kc < 4; kc++) {
        if (kc < 3) prefetch(kc + 1);
        if (kc < 3) cp_wait<1>(); else cp_wait<0>();
        __syncthreads();

        const char* bufA = sm + SM3_AH + (kc & 1) * CHUNKB;
        const char* bufL = sm + SM3_AL + (kc & 1) * CHUNKB;
        const char* bufB = sm + SM3_BH + (kc & 1) * CHUNKB;
        const char* bufC = sm + SM3_BL + (kc & 1) * CHUNKB;

        #pragma unroll
        for (int ks = 0; ks < 2; ks++) {
            int kb = ks * 32;
            uint32_t bh[4][2], bl[4][2];
            #pragma unroll
            for (int nt = 0; nt < 4; nt++) {
                int nrow = wn + nt * 8 + g;
                const char* ph = bufB + nrow * ROWB3 + kb + t * 4;
                const char* pl = bufC + nrow * ROWB3 + kb + t * 4;
                bh[nt][0] = *(const uint32_t*)(ph);
                bh[nt][1] = *(const uint32_t*)(ph + 16);
                bl[nt][0] = *(const uint32_t*)(pl);
                bl[nt][1] = *(const uint32_t*)(pl + 16);
            }
            #pragma unroll
            for (int mt = 0; mt < 4; mt++) {
                int mrow = wm + mt * 16 + g;
                const char* ph = bufA + mrow * ROWB3 + kb + t * 4;
                const char* pl = bufL + mrow * ROWB3 + kb + t * 4;
                uint32_t ah0 = *(const uint32_t*)(ph);
                uint32_t ah1 = *(const uint32_t*)(ph + 8 * ROWB3);
                uint32_t ah2 = *(const uint32_t*)(ph + 16);
                uint32_t ah3 = *(const uint32_t*)(ph + 8 * ROWB3 + 16);
                uint32_t al0 = *(const uint32_t*)(pl);
                uint32_t al1 = *(const uint32_t*)(pl + 8 * ROWB3);
                uint32_t al2 = *(const uint32_t*)(pl + 16);
                uint32_t al3 = *(const uint32_t*)(pl + 8 * ROWB3 + 16);
                #pragma unroll
                for (int nt = 0; nt < 4; nt++) {
                    mma_bf16(acc[mt][nt], ah0, ah1, ah2, ah3, bh[nt][0], bh[nt][1]);
                    mma_bf16(acc[mt][nt], ah0, ah1, ah2, ah3, bl[nt][0], bl[nt][1]);
                    mma_bf16(acc[mt][nt], al0, al1, al2, al3, bh[nt][0], bh[nt][1]);
                }
            }
        }
        __syncthreads();   // chunk reads done before buffer reuse
    }

    // ---- epilogue: write D as fp16 to g_xwh ----
    #pragma unroll
    for (int mt = 0; mt < 4; mt++) {
        int row = r0 + wm + mt * 16 + g;
        #pragma unroll
        for (int nt = 0; nt < 4; nt++) {
            int col = wn + nt * 8 + t * 2;
            if (row < NN) {
                __half2 p = __floats2half2_rn(acc[mt][nt][0], acc[mt][nt][1]);
                *(uint32_t*)((char*)g_xwh + ((size_t)row * DH + col) * 2) =
                    *(uint32_t*)&p;
            }
            if (row + 8 < NN) {
                __half2 p = __floats2half2_rn(acc[mt][nt][2], acc[mt][nt][3]);
                *(uint32_t*)((char*)g_xwh + ((size_t)(row + 8) * DH + col) * 2) =
                    *(uint32_t*)&p;
            }
        }
    }
}

// ---------------- aggregation: h = relu( Ahat @ xw + b ) ----------------
// one warp per node, lane handles 4 cols (uint2, 8B); 4-edge guarded unroll
// -> 4 independent gathers in flight. Intermediate layers emit bf16 hi/lo;
// last layer fuses the FC head.
__global__ __launch_bounds__(256) void k_agg(const float* __restrict__ b,
                                             const float* __restrict__ Wfc,
                                             const float* __restrict__ bfc,
                                             float* __restrict__ out) {
    int warp = (blockIdx.x * blockDim.x + threadIdx.x) >> 5;
    int lane = threadIdx.x & 31;
    if (warp >= NN) return;
    int node = warp;

    const uint2* xw = (const uint2*)g_xwh;   // 4 halves per uint2

    float dv   = g_dinv[node];
    float self = dv * dv;

    uint2 sraw = xw[node * 32 + lane];
    float2 f01 = __half22float2(*(__half2*)&sraw.x);
    float2 f23 = __half22float2(*(__half2*)&sraw.y);
    float4 acc = make_float4(f01.x * self, f01.y * self,
                             f23.x * self, f23.y * self);

    int start = g_off[node];
    int m     = g_cnt[node];

    for (int j = 0; j < m; j += 4) {
        int2 e0 = g_edge[start + j];
        int2 e1 = (j + 1 < m) ? g_edge[start + j + 1] : make_int2(0, 0);
        int2 e2 = (j + 2 < m) ? g_edge[start + j + 2] : make_int2(0, 0);
        int2 e3 = (j + 3 < m) ? g_edge[start + j + 3] : make_int2(0, 0);
        uint2 r0 = xw[(size_t)e0.x * 32 + lane];
        uint2 r1 = xw[(size_t)e1.x * 32 + lane];
        uint2 r2 = xw[(size_t)e2.x * 32 + lane];
        uint2 r3 = xw[(size_t)e3.x * 32 + lane];
        float n0 = __int_as_float(e0.y);
        float n1 = __int_as_float(e1.y);
        float n2 = __int_as_float(e2.y);
        float n3 = __int_as_float(e3.y);
        float2 a01 = __half22float2(*(__half2*)&r0.x);
        float2 a23 = __half22float2(*(__half2*)&r0.y);
        float2 b01 = __half22float2(*(__half2*)&r1.x);
        float2 b23 = __half22float2(*(__half2*)&r1.y);
        float2 c01 = __half22float2(*(__half2*)&r2.x);
        float2 c23 = __half22float2(*(__half2*)&r2.y);
        float2 d01 = __half22float2(*(__half2*)&r3.x);
        float2 d23 = __half22float2(*(__half2*)&r3.y);
        acc.x += a01.x * n0 + b01.x * n1 + c01.x * n2 + d01.x * n3;
        acc.y += a01.y * n0 + b01.y * n1 + c01.y * n2 + d01.y * n3;
        acc.z += a23.x * n0 + b23.x * n1 + c23.x * n2 + d23.x * n3;
        acc.w += a23.y * n0 + b23.y * n1 + c23.y * n2 + d23.y * n3;
    }

    float4 bb = ((const float4*)b)[lane];
    acc.x = fmaxf(acc.x + bb.x, 0.0f);
    acc.y = fmaxf(acc.y + bb.y, 0.0f);
    acc.z = fmaxf(acc.z + bb.z, 0.0f);
    acc.w = fmaxf(acc.w + bb.w, 0.0f);

    if (Wfc) {
        float4 w = ((const float4*)Wfc)[lane];
        float sum = acc.x * w.x + acc.y * w.y + acc.z * w.z + acc.w * w.w;
        #pragma unroll
        for (int d = 16; d > 0; d >>= 1)
            sum += __shfl_xor_sync(0xFFFFFFFFu, sum, d);
        if (lane == 0) out[node] = sum + bfc[0];
    } else {
        // emit h pre-split as bf16 hi/lo
        float rx, ry, rz, rw, z;
        uint32_t hx = bsplit_hi(acc.x, rx), hy = bsplit_hi(acc.y, ry);
        uint32_t hz = bsplit_hi(acc.z, rz), hw = bsplit_hi(acc.w, rw);
        uint32_t lx = bsplit_hi(rx, z), ly = bsplit_hi(ry, z);
        uint32_t lz = bsplit_hi(rz, z), lw = bsplit_hi(rw, z);
        ((uint2*)g_ah)[node * 32 + lane] =
            make_uint2(hx | (hy << 16), hz | (hw << 16));
        ((uint2*)g_al)[node * 32 + lane] =
            make_uint2(lx | (ly << 16), lz | (lw << 16));
    }
}

// ---------------- launch -------------------------------------------------
extern "C" void kernel_launch(void* const* d_in, const int* in_sizes, int n_in,
                              void* d_out, int out_size) {
    const float* x    = (const float*)d_in[0];
    const void*  ei   = d_in[1];
    const float* W1   = (const float*)d_in[2];
    const float* b1   = (const float*)d_in[3];
    const float* W2   = (const float*)d_in[4];
    const float* b2   = (const float*)d_in[5];
    const float* W3   = (const float*)d_in[6];
    const float* b3   = (const float*)d_in[7];
    const float* Wfc  = (const float*)d_in[8];
    const float* bfc  = (const float*)d_in[9];
    float* out = (float*)d_out;

    static int smem_set = 0;
    if (!smem_set) {
        cudaFuncSetAttribute(k_gemm_mma,
                             cudaFuncAttributeMaxDynamicSharedMemorySize,
                             SM3_TOTAL);
        smem_set = 1;
    }

    const int TB = 256;
    int ge = (EE + TB - 1) / TB;
    int gn = (NN + TB - 1) / TB;
    int gsx = (NN * DH / 4 + TB - 1) / TB;
    int ggemm = (NN + 127) / 128;
    int gwarp = (NN * 32 + TB - 1) / TB;

    k_splitx<<<gsx, TB>>>(x);                                // 1
    dim3 wgrid(DH, 3);
    k_wprep3<<<wgrid, DH>>>(W1, W2, W3);                     // 2
    k_dz<<<gn, TB>>>(ei);                                    // 3
    k_gemm_mma<<<ggemm, 256, SM3_TOTAL>>>(0);                // 4 <- profiled
    k_convert_count<<<ge, TB>>>(ei);                         // 5
    k_scan<<<1, 1024>>>();                                   // 6
    k_scatter<<<ge, TB>>>();                                 // 7
    k_agg<<<gwarp, TB>>>(b1, nullptr, nullptr, nullptr);     // 8
    k_gemm_mma<<<ggemm, 256, SM3_TOTAL>>>(1);                // 9
    k_agg<<<gwarp, TB>>>(b2, nullptr, nullptr, nullptr);     // 10
    k_gemm_mma<<<ggemm, 256, SM3_TOTAL>>>(2);                // 11
    k_agg<<<gwarp, TB>>>(b3, Wfc, bfc, out);                 // 12
}

// round 15
// speedup vs baseline: 1.0669x; 1.0669x over previous
#include <cuda_runtime.h>
#include <cuda_bf16.h>
#include <cuda_fp16.h>
#include <cstdint>

#define NN   50000
#define EE   800000
#define DH   128

// ---------------- device scratch (zero-initialized at module load; ------
// k_cleanup restores g_cnt/g_pos to zero at the end of every call) -------
__device__ int    g_src[EE];
__device__ int    g_dst[EE];
__device__ int    g_cnt[NN];
__device__ int    g_off[NN];
__device__ int    g_pos[NN];
__device__ float  g_dinv[NN];
__device__ int2   g_edge[EE];                 // {src, norm bits} per CSR slot
__device__ __half g_xwh[NN * DH];             // GEMM output, fp16 gather payload
__device__ unsigned short g_ah[NN * DH];      // activations, bf16 hi
__device__ unsigned short g_al[NN * DH];      // activations, bf16 lo
__device__ unsigned short g_wh[3 * DH * DH];  // W^T hi per layer, [l][n][k]
__device__ unsigned short g_wl[3 * DH * DH];  // W^T lo per layer

__device__ __forceinline__ uint32_t bsplit_hi(float x, float& rem) {
    __nv_bfloat16 hb = __float2bfloat16_rn(x);
    rem = x - __bfloat162float(hb);
    return (uint32_t)__bfloat16_as_ushort(hb);
}

__device__ __forceinline__ uint32_t smem_u32(const void* p) {
    uint32_t a;
    asm("{ .reg .u64 t; cvta.to.shared.u64 t, %1; cvt.u32.u64 %0, t; }" : "=r"(a) : "l"(p));
    return a;
}
__device__ __forceinline__ void cp16(uint32_t dst, const void* src) {
    asm volatile("cp.async.ca.shared.global [%0], [%1], 16;"
                 :: "r"(dst), "l"(__cvta_generic_to_global(src)));
}
__device__ __forceinline__ void cp_commit() {
    asm volatile("cp.async.commit_group;");
}
template <int N>
__device__ __forceinline__ void cp_wait() {
    asm volatile("cp.async.wait_group %0;" :: "n"(N));
}

// ---------------- prep: splitx | wprep | convert+count (range-split) ----
#define GSX 6250                   // NN*DH/4 float4 elements / 256
#define GW  192                    // 3*DH*DH / 256
#define GE  3125                   // EE / 256

__global__ __launch_bounds__(256) void k_prep(const float* __restrict__ x,
                                              const float* __restrict__ W1,
                                              const float* __restrict__ W2,
                                              const float* __restrict__ W3,
                                              const void* ei) {
    int bid = blockIdx.x;
    int tid = threadIdx.x;

    if (bid < GSX) {
        // ---- split x into bf16 hi/lo ----
        int i = bid * 256 + tid;      // one float4 per thread
        float4 v = ((const float4*)x)[i];
        float rx, ry, rz, rw, z;
        uint32_t hx = bsplit_hi(v.x, rx), hy = bsplit_hi(v.y, ry);
        uint32_t hz = bsplit_hi(v.z, rz), hw = bsplit_hi(v.w, rw);
        uint32_t lx = bsplit_hi(rx, z), ly = bsplit_hi(ry, z);
        uint32_t lz = bsplit_hi(rz, z), lw = bsplit_hi(rw, z);
        ((uint2*)g_ah)[i] = make_uint2(hx | (hy << 16), hz | (hw << 16));
        ((uint2*)g_al)[i] = make_uint2(lx | (ly << 16), lz | (lw << 16));
    } else if (bid < GSX + GW) {
        // ---- W^T + bf16 split, all 3 layers ----
        int idx = (bid - GSX) * 256 + tid;
        int l = idx / (DH * DH);
        int rem = idx - l * (DH * DH);
        int n = rem / DH, k = rem - (rem / DH) * DH;
        const float* W = (l == 0) ? W1 : (l == 1) ? W2 : W3;
        float v = W[k * DH + n];
        float r;
        uint32_t h = bsplit_hi(v, r);
        uint32_t lo = bsplit_hi(r, v);
        g_wh[idx] = (unsigned short)h;
        g_wl[idx] = (unsigned short)lo;
    } else {
        // ---- edge convert + degree count (per-block dtype detect) ----
        const unsigned* p = (const unsigned*)ei;
        unsigned vv = (tid < 64) ? p[2 * tid + 1] : 0u;
        int any = __syncthreads_or((int)(vv != 0u));
        int is64 = !any;
        int e = (bid - GSX - GW) * 256 + tid;
        int s, d;
        if (is64) {
            const long long* q = (const long long*)ei;
            s = (int)q[e]; d = (int)q[EE + e];
        } else {
            const int* q = (const int*)ei;
            s = q[e]; d = q[EE + e];
        }
        g_src[e] = s; g_dst[e] = d;
        atomicAdd(&g_cnt[d], 1);
    }
}

// ---------------- scan body (256 threads, one block) --------------------
__device__ void scan_body() {
    __shared__ int wsum[8];
    const int C = (NN + 255) / 256;
    int t = threadIdx.x, lane = t & 31, wid = t >> 5;
    int beg = t * C;
    int end = min(beg + C, NN);
    int s = 0;
    for (int i = beg; i < end; i++) s += g_cnt[i];
    int v = s;
    #pragma unroll
    for (int d = 1; d < 32; d <<= 1) {
        int u = __shfl_up_sync(0xFFFFFFFFu, v, d);
        if (lane >= d) v += u;
    }
    if (lane == 31) wsum[wid] = v;
    __syncthreads();
    if (wid == 0) {
        int w = (lane < 8) ? wsum[lane] : 0;
        #pragma unroll
        for (int d = 1; d < 8; d <<= 1) {
            int u = __shfl_up_sync(0xFFFFFFFFu, w, d);
            if (lane >= d) w += u;
        }
        if (lane < 8) wsum[lane] = w;
    }
    __syncthreads();
    int run = v - s + (wid ? wsum[wid - 1] : 0);
    for (int i = beg; i < end; i++) {
        int c = g_cnt[i];
        g_off[i] = run;
        g_dinv[i] = rsqrtf((float)c + 1.0f);
        run += c;
    }
}

// ---------------- bf16x3 mma GEMM body ----------------------------------
#define ROWB3  80
#define CHUNKB (128 * ROWB3)
#define SM3_AH 0
#define SM3_AL (SM3_AH + 2 * CHUNKB)
#define SM3_BH (SM3_AL + 2 * CHUNKB)
#define SM3_BL (SM3_BH + 2 * CHUNKB)
#define SM3_TOTAL (SM3_BL + 2 * CHUNKB)   // 81920 B

__device__ __forceinline__ void mma_bf16(float* d, uint32_t a0, uint32_t a1,
                                         uint32_t a2, uint32_t a3,
                                         uint32_t b0, uint32_t b1) {
    asm volatile(
        "mma.sync.aligned.m16n8k16.row.col.f32.bf16.bf16.f32 "
        "{%0,%1,%2,%3}, {%4,%5,%6,%7}, {%8,%9}, {%0,%1,%2,%3};"
        : "+f"(d[0]), "+f"(d[1]), "+f"(d[2]), "+f"(d[3])
        : "r"(a0), "r"(a1), "r"(a2), "r"(a3), "r"(b0), "r"(b1));
}

__device__ void gemm_body(int layer, int bid, char* sm) {
    uint32_t smb = smem_u32(sm);
    int tid  = threadIdx.x;
    int wid  = tid >> 5;
    int lane = tid & 31;
    int r0   = bid * 128;

    const unsigned short* WH = g_wh + layer * DH * DH;
    const unsigned short* WL = g_wl + layer * DH * DH;

    int cr = tid >> 1;
    int hf = tid & 1;
    int arow = min(r0 + cr, NN - 1);

    auto prefetch = [&](int kc) {
        int buf = kc & 1;
        size_t aoff = (size_t)arow * DH + kc * 32 + hf * 16;
        size_t boff = (size_t)cr   * DH + kc * 32 + hf * 16;
        uint32_t dA = smb + SM3_AH + buf * CHUNKB + cr * ROWB3 + hf * 32;
        uint32_t dL = smb + SM3_AL + buf * CHUNKB + cr * ROWB3 + hf * 32;
        uint32_t dB = smb + SM3_BH + buf * CHUNKB + cr * ROWB3 + hf * 32;
        uint32_t dC = smb + SM3_BL + buf * CHUNKB + cr * ROWB3 + hf * 32;
        cp16(dA,      g_ah + aoff);
        cp16(dA + 16, g_ah + aoff + 8);
        cp16(dL,      g_al + aoff);
        cp16(dL + 16, g_al + aoff + 8);
        cp16(dB,      WH + boff);
        cp16(dB + 16, WH + boff + 8);
        cp16(dC,      WL + boff);
        cp16(dC + 16, WL + boff + 8);
        cp_commit();
    };

    int wm = (wid & 1) * 64;
    int wn = (wid >> 1) * 32;
    int g  = lane >> 2;
    int t  = lane & 3;

    float acc[4][4][4];
    #pragma unroll
    for (int mt = 0; mt < 4; mt++)
        #pragma unroll
        for (int nt = 0; nt < 4; nt++)
            #pragma unroll
            for (int q = 0; q < 4; q++) acc[mt][nt][q] = 0.0f;

    prefetch(0);

    #pragma unroll
    for (int kc = 0; kc < 4; kc++) {
        if (kc < 3) prefetch(kc + 1);
        if (kc < 3) cp_wait<1>(); else cp_wait<0>();
        __syncthreads();

        const char* bufA = sm + SM3_AH + (kc & 1) * CHUNKB;
        const char* bufL = sm + SM3_AL + (kc & 1) * CHUNKB;
        const char* bufB = sm + SM3_BH + (kc & 1) * CHUNKB;
        const char* bufC = sm + SM3_BL + (kc & 1) * CHUNKB;

        #pragma unroll
        for (int ks = 0; ks < 2; ks++) {
            int kb = ks * 32;
            uint32_t bh[4][2], bl[4][2];
            #pragma unroll
            for (int nt = 0; nt < 4; nt++) {
                int nrow = wn + nt * 8 + g;
                const char* ph = bufB + nrow * ROWB3 + kb + t * 4;
                const char* pl = bufC + nrow * ROWB3 + kb + t * 4;
                bh[nt][0] = *(const uint32_t*)(ph);
                bh[nt][1] = *(const uint32_t*)(ph + 16);
                bl[nt][0] = *(const uint32_t*)(pl);
                bl[nt][1] = *(const uint32_t*)(pl + 16);
            }
            #pragma unroll
            for (int mt = 0; mt < 4; mt++) {
                int mrow = wm + mt * 16 + g;
                const char* ph = bufA + mrow * ROWB3 + kb + t * 4;
                const char* pl = bufL + mrow * ROWB3 + kb + t * 4;
                uint32_t ah0 = *(const uint32_t*)(ph);
                uint32_t ah1 = *(const uint32_t*)(ph + 8 * ROWB3);
                uint32_t ah2 = *(const uint32_t*)(ph + 16);
                uint32_t ah3 = *(const uint32_t*)(ph + 8 * ROWB3 + 16);
                uint32_t al0 = *(const uint32_t*)(pl);
                uint32_t al1 = *(const uint32_t*)(pl + 8 * ROWB3);
                uint32_t al2 = *(const uint32_t*)(pl + 16);
                uint32_t al3 = *(const uint32_t*)(pl + 8 * ROWB3 + 16);
                #pragma unroll
                for (int nt = 0; nt < 4; nt++) {
                    mma_bf16(acc[mt][nt], ah0, ah1, ah2, ah3, bh[nt][0], bh[nt][1]);
                    mma_bf16(acc[mt][nt], ah0, ah1, ah2, ah3, bl[nt][0], bl[nt][1]);
                    mma_bf16(acc[mt][nt], al0, al1, al2, al3, bh[nt][0], bh[nt][1]);
                }
            }
        }
        __syncthreads();
    }

    #pragma unroll
    for (int mt = 0; mt < 4; mt++) {
        int row = r0 + wm + mt * 16 + g;
        #pragma unroll
        for (int nt = 0; nt < 4; nt++) {
            int col = wn + nt * 8 + t * 2;
            if (row < NN) {
                __half2 p = __floats2half2_rn(acc[mt][nt][0], acc[mt][nt][1]);
                *(uint32_t*)((char*)g_xwh + ((size_t)row * DH + col) * 2) =
                    *(uint32_t*)&p;
            }
            if (row + 8 < NN) {
                __half2 p = __floats2half2_rn(acc[mt][nt][2], acc[mt][nt][3]);
                *(uint32_t*)((char*)g_xwh + ((size_t)(row + 8) * DH + col) * 2) =
                    *(uint32_t*)&p;
            }
        }
    }
}

#define GGEMM 391   // ceil(NN / 128)

// gemm for layer 0, with the CSR scan riding along as block GGEMM
__global__ __launch_bounds__(256, 2) void k_gemm_scan() {
    extern __shared__ char sm[];
    if (blockIdx.x < GGEMM) gemm_body(0, blockIdx.x, sm);
    else                    scan_body();
}

__global__ __launch_bounds__(256, 2) void k_gemm_mma(int layer) {
    extern __shared__ char sm[];
    gemm_body(layer, blockIdx.x, sm);
}

// ---------------- scatter ------------------------------------------------
__global__ void k_scatter() {
    int e = blockIdx.x * blockDim.x + threadIdx.x;
    if (e >= EE) return;
    int s = g_src[e];
    int d = g_dst[e];
    int p = g_off[d] + atomicAdd(&g_pos[d], 1);
    g_edge[p] = make_int2(s, __float_as_int(g_dinv[s] * g_dinv[d]));
}

// ---------------- aggregation (R13 form: 2-edge unroll) ------------------
__global__ __launch_bounds__(256) void k_agg(const float* __restrict__ b,
                                             const float* __restrict__ Wfc,
                                             const float* __restrict__ bfc,
                                             float* __restrict__ out) {
    int warp = (blockIdx.x * blockDim.x + threadIdx.x) >> 5;
    int lane = threadIdx.x & 31;
    if (warp >= NN) return;
    int node = warp;

    const uint2* xw = (const uint2*)g_xwh;

    float dv   = g_dinv[node];
    float self = dv * dv;

    uint2 sraw = xw[node * 32 + lane];
    float2 f01 = __half22float2(*(__half2*)&sraw.x);
    float2 f23 = __half22float2(*(__half2*)&sraw.y);
    float4 acc = make_float4(f01.x * self, f01.y * self,
                             f23.x * self, f23.y * self);

    int start = g_off[node];
    int m     = g_cnt[node];

    int j = 0;
    for (; j + 1 < m; j += 2) {
        int2 e0 = g_edge[start + j];
        int2 e1 = g_edge[start + j + 1];
        uint2 r0 = xw[(size_t)e0.x * 32 + lane];
        uint2 r1 = xw[(size_t)e1.x * 32 + lane];
        float n0 = __int_as_float(e0.y);
        float n1 = __int_as_float(e1.y);
        float2 a01 = __half22float2(*(__half2*)&r0.x);
        float2 a23 = __half22float2(*(__half2*)&r0.y);
        float2 b01 = __half22float2(*(__half2*)&r1.x);
        float2 b23 = __half22float2(*(__half2*)&r1.y);
        acc.x += a01.x * n0 + b01.x * n1;
        acc.y += a01.y * n0 + b01.y * n1;
        acc.z += a23.x * n0 + b23.x * n1;
        acc.w += a23.y * n0 + b23.y * n1;
    }
    if (j < m) {
        int2 e0 = g_edge[start + j];
        uint2 r0 = xw[(size_t)e0.x * 32 + lane];
        float n0 = __int_as_float(e0.y);
        float2 a01 = __half22float2(*(__half2*)&r0.x);
        float2 a23 = __half22float2(*(__half2*)&r0.y);
        acc.x += a01.x * n0;
        acc.y += a01.y * n0;
        acc.z += a23.x * n0;
        acc.w += a23.y * n0;
    }

    float4 bb = ((const float4*)b)[lane];
    acc.x = fmaxf(acc.x + bb.x, 0.0f);
    acc.y = fmaxf(acc.y + bb.y, 0.0f);
    acc.z = fmaxf(acc.z + bb.z, 0.0f);
    acc.w = fmaxf(acc.w + bb.w, 0.0f);

    if (Wfc) {
        float4 w = ((const float4*)Wfc)[lane];
        float sum = acc.x * w.x + acc.y * w.y + acc.z * w.z + acc.w * w.w;
        #pragma unroll
        for (int d = 16; d > 0; d >>= 1)
            sum += __shfl_xor_sync(0xFFFFFFFFu, sum, d);
        if (lane == 0) out[node] = sum + bfc[0];
    } else {
        float rx, ry, rz, rw, z;
        uint32_t hx = bsplit_hi(acc.x, rx), hy = bsplit_hi(acc.y, ry);
        uint32_t hz = bsplit_hi(acc.z, rz), hw = bsplit_hi(acc.w, rw);
        uint32_t lx = bsplit_hi(rx, z), ly = bsplit_hi(ry, z);
        uint32_t lz = bsplit_hi(rz, z), lw = bsplit_hi(rw, z);
        ((uint2*)g_ah)[node * 32 + lane] =
            make_uint2(hx | (hy << 16), hz | (hw << 16));
        ((uint2*)g_al)[node * 32 + lane] =
            make_uint2(lx | (ly << 16), lz | (lw << 16));
    }
}

// ---------------- cleanup: restore zero invariant ------------------------
__global__ void k_cleanup() {
    int i = blockIdx.x * blockDim.x + threadIdx.x;
    if (i < NN) { g_cnt[i] = 0; g_pos[i] = 0; }
}

// ---------------- launch -------------------------------------------------
extern "C" void kernel_launch(void* const* d_in, const int* in_sizes, int n_in,
                              void* d_out, int out_size) {
    const float* x    = (const float*)d_in[0];
    const void*  ei   = d_in[1];
    const float* W1   = (const float*)d_in[2];
    const float* b1   = (const float*)d_in[3];
    const float* W2   = (const float*)d_in[4];
    const float* b2   = (const float*)d_in[5];
    const float* W3   = (const float*)d_in[6];
    const float* b3   = (const float*)d_in[7];
    const float* Wfc  = (const float*)d_in[8];
    const float* bfc  = (const float*)d_in[9];
    float* out = (float*)d_out;

    static int smem_set = 0;
    if (!smem_set) {
        cudaFuncSetAttribute(k_gemm_scan,
                             cudaFuncAttributeMaxDynamicSharedMemorySize,
                             SM3_TOTAL);
        cudaFuncSetAttribute(k_gemm_mma,
                             cudaFuncAttributeMaxDynamicSharedMemorySize,
                             SM3_TOTAL);
        smem_set = 1;
    }

    const int TB = 256;
    int ge = (EE + TB - 1) / TB;
    int gn = (NN + TB - 1) / TB;
    int gwarp = (NN * 32 + TB - 1) / TB;

    k_prep<<<GSX + GW + GE, TB>>>(x, W1, W2, W3, ei);          // 1
    k_gemm_scan<<<GGEMM + 1, 256, SM3_TOTAL>>>();              // 2
    k_scatter<<<ge, TB>>>();                                   // 3
    k_agg<<<gwarp, TB>>>(b1, nullptr, nullptr, nullptr);       // 4 <- profiled
    k_gemm_mma<<<GGEMM, 256, SM3_TOTAL>>>(1);                  // 5
    k_agg<<<gwarp, TB>>>(b2, nullptr, nullptr, nullptr);       // 6
    k_gemm_mma<<<GGEMM, 256, SM3_TOTAL>>>(2);                  // 7
    k_agg<<<gwarp, TB>>>(b3, Wfc, bfc, out);                   // 8
    k_cleanup<<<gn, TB>>>();                                   // 9
}

// round 16
// speedup vs baseline: 1.0982x; 1.0293x over previous
#include <cuda_runtime.h>
#include <cuda_bf16.h>
#include <cuda_fp16.h>
#include <cstdint>

#define NN   50000
#define EE   800000
#define DH   128

// ---------------- device scratch (zero-initialized at module load; ------
// k_cleanup restores g_cnt/g_pos to zero at the end of every call) -------
__device__ int    g_src[EE];
__device__ int    g_dst[EE];
__device__ int    g_cnt[NN];
__device__ int    g_off[NN];
__device__ int    g_pos[NN];
__device__ float  g_dinv[NN];
__device__ int2   g_edge[EE + 4];             // {src, norm bits}; +4 pad for int4 tail
__device__ __half g_xwh[NN * DH];             // GEMM output, fp16 gather payload
__device__ unsigned short g_ah[NN * DH];      // activations, bf16 hi
__device__ unsigned short g_al[NN * DH];      // activations, bf16 lo
__device__ unsigned short g_wh[3 * DH * DH];  // W^T hi per layer, [l][n][k]
__device__ unsigned short g_wl[3 * DH * DH];  // W^T lo per layer

__device__ __forceinline__ uint32_t bsplit_hi(float x, float& rem) {
    __nv_bfloat16 hb = __float2bfloat16_rn(x);
    rem = x - __bfloat162float(hb);
    return (uint32_t)__bfloat16_as_ushort(hb);
}

__device__ __forceinline__ uint32_t smem_u32(const void* p) {
    uint32_t a;
    asm("{ .reg .u64 t; cvta.to.shared.u64 t, %1; cvt.u32.u64 %0, t; }" : "=r"(a) : "l"(p));
    return a;
}
__device__ __forceinline__ void cp16(uint32_t dst, const void* src) {
    asm volatile("cp.async.ca.shared.global [%0], [%1], 16;"
                 :: "r"(dst), "l"(__cvta_generic_to_global(src)));
}
__device__ __forceinline__ void cp_commit() {
    asm volatile("cp.async.commit_group;");
}
template <int N>
__device__ __forceinline__ void cp_wait() {
    asm volatile("cp.async.wait_group %0;" :: "n"(N));
}

// ---------------- prep: splitx | wprep | convert+count (range-split) ----
#define GSX 6250                   // NN*DH/4 float4 elements / 256
#define GW  192                    // 3*DH*DH / 256
#define GE  3125                   // EE / 256

__global__ __launch_bounds__(256) void k_prep(const float* __restrict__ x,
                                              const float* __restrict__ W1,
                                              const float* __restrict__ W2,
                                              const float* __restrict__ W3,
                                              const void* ei) {
    int bid = blockIdx.x;
    int tid = threadIdx.x;

    if (bid < GSX) {
        int i = bid * 256 + tid;      // one float4 per thread
        float4 v = ((const float4*)x)[i];
        float rx, ry, rz, rw, z;
        uint32_t hx = bsplit_hi(v.x, rx), hy = bsplit_hi(v.y, ry);
        uint32_t hz = bsplit_hi(v.z, rz), hw = bsplit_hi(v.w, rw);
        uint32_t lx = bsplit_hi(rx, z), ly = bsplit_hi(ry, z);
        uint32_t lz = bsplit_hi(rz, z), lw = bsplit_hi(rw, z);
        ((uint2*)g_ah)[i] = make_uint2(hx | (hy << 16), hz | (hw << 16));
        ((uint2*)g_al)[i] = make_uint2(lx | (ly << 16), lz | (lw << 16));
    } else if (bid < GSX + GW) {
        int idx = (bid - GSX) * 256 + tid;
        int l = idx / (DH * DH);
        int rem = idx - l * (DH * DH);
        int n = rem / DH, k = rem - (rem / DH) * DH;
        const float* W = (l == 0) ? W1 : (l == 1) ? W2 : W3;
        float v = W[k * DH + n];
        float r;
        uint32_t h = bsplit_hi(v, r);
        uint32_t lo = bsplit_hi(r, v);
        g_wh[idx] = (unsigned short)h;
        g_wl[idx] = (unsigned short)lo;
    } else {
        const unsigned* p = (const unsigned*)ei;
        unsigned vv = (tid < 64) ? p[2 * tid + 1] : 0u;
        int any = __syncthreads_or((int)(vv != 0u));
        int is64 = !any;
        int e = (bid - GSX - GW) * 256 + tid;
        int s, d;
        if (is64) {
            const long long* q = (const long long*)ei;
            s = (int)q[e]; d = (int)q[EE + e];
        } else {
            const int* q = (const int*)ei;
            s = q[e]; d = q[EE + e];
        }
        g_src[e] = s; g_dst[e] = d;
        atomicAdd(&g_cnt[d], 1);
    }
}

// ---------------- scan body (256 threads, one block) --------------------
__device__ void scan_body() {
    __shared__ int wsum[8];
    const int C = (NN + 255) / 256;
    int t = threadIdx.x, lane = t & 31, wid = t >> 5;
    int beg = t * C;
    int end = min(beg + C, NN);
    int s = 0;
    for (int i = beg; i < end; i++) s += g_cnt[i];
    int v = s;
    #pragma unroll
    for (int d = 1; d < 32; d <<= 1) {
        int u = __shfl_up_sync(0xFFFFFFFFu, v, d);
        if (lane >= d) v += u;
    }
    if (lane == 31) wsum[wid] = v;
    __syncthreads();
    if (wid == 0) {
        int w = (lane < 8) ? wsum[lane] : 0;
        #pragma unroll
        for (int d = 1; d < 8; d <<= 1) {
            int u = __shfl_up_sync(0xFFFFFFFFu, w, d);
            if (lane >= d) w += u;
        }
        if (lane < 8) wsum[lane] = w;
    }
    __syncthreads();
    int run = v - s + (wid ? wsum[wid - 1] : 0);
    for (int i = beg; i < end; i++) {
        int c = g_cnt[i];
        g_off[i] = run;
        g_dinv[i] = rsqrtf((float)c + 1.0f);
        run += c;
    }
}

// ---------------- bf16x3 mma GEMM body ----------------------------------
#define ROWB3  80
#define CHUNKB (128 * ROWB3)
#define SM3_AH 0
#define SM3_AL (SM3_AH + 2 * CHUNKB)
#define SM3_BH (SM3_AL + 2 * CHUNKB)
#define SM3_BL (SM3_BH + 2 * CHUNKB)
#define SM3_TOTAL (SM3_BL + 2 * CHUNKB)   // 81920 B

__device__ __forceinline__ void mma_bf16(float* d, uint32_t a0, uint32_t a1,
                                         uint32_t a2, uint32_t a3,
                                         uint32_t b0, uint32_t b1) {
    asm volatile(
        "mma.sync.aligned.m16n8k16.row.col.f32.bf16.bf16.f32 "
        "{%0,%1,%2,%3}, {%4,%5,%6,%7}, {%8,%9}, {%0,%1,%2,%3};"
        : "+f"(d[0]), "+f"(d[1]), "+f"(d[2]), "+f"(d[3])
        : "r"(a0), "r"(a1), "r"(a2), "r"(a3), "r"(b0), "r"(b1));
}

__device__ void gemm_body(int layer, int bid, char* sm) {
    uint32_t smb = smem_u32(sm);
    int tid  = threadIdx.x;
    int wid  = tid >> 5;
    int lane = tid & 31;
    int r0   = bid * 128;

    const unsigned short* WH = g_wh + layer * DH * DH;
    const unsigned short* WL = g_wl + layer * DH * DH;

    int cr = tid >> 1;
    int hf = tid & 1;
    int arow = min(r0 + cr, NN - 1);

    auto prefetch = [&](int kc) {
        int buf = kc & 1;
        size_t aoff = (size_t)arow * DH + kc * 32 + hf * 16;
        size_t boff = (size_t)cr   * DH + kc * 32 + hf * 16;
        uint32_t dA = smb + SM3_AH + buf * CHUNKB + cr * ROWB3 + hf * 32;
        uint32_t dL = smb + SM3_AL + buf * CHUNKB + cr * ROWB3 + hf * 32;
        uint32_t dB = smb + SM3_BH + buf * CHUNKB + cr * ROWB3 + hf * 32;
        uint32_t dC = smb + SM3_BL + buf * CHUNKB + cr * ROWB3 + hf * 32;
        cp16(dA,      g_ah + aoff);
        cp16(dA + 16, g_ah + aoff + 8);
        cp16(dL,      g_al + aoff);
        cp16(dL + 16, g_al + aoff + 8);
        cp16(dB,      WH + boff);
        cp16(dB + 16, WH + boff + 8);
        cp16(dC,      WL + boff);
        cp16(dC + 16, WL + boff + 8);
        cp_commit();
    };

    int wm = (wid & 1) * 64;
    int wn = (wid >> 1) * 32;
    int g  = lane >> 2;
    int t  = lane & 3;

    float acc[4][4][4];
    #pragma unroll
    for (int mt = 0; mt < 4; mt++)
        #pragma unroll
        for (int nt = 0; nt < 4; nt++)
            #pragma unroll
            for (int q = 0; q < 4; q++) acc[mt][nt][q] = 0.0f;

    prefetch(0);

    #pragma unroll
    for (int kc = 0; kc < 4; kc++) {
        if (kc < 3) prefetch(kc + 1);
        if (kc < 3) cp_wait<1>(); else cp_wait<0>();
        __syncthreads();

        const char* bufA = sm + SM3_AH + (kc & 1) * CHUNKB;
        const char* bufL = sm + SM3_AL + (kc & 1) * CHUNKB;
        const char* bufB = sm + SM3_BH + (kc & 1) * CHUNKB;
        const char* bufC = sm + SM3_BL + (kc & 1) * CHUNKB;

        #pragma unroll
        for (int ks = 0; ks < 2; ks++) {
            int kb = ks * 32;
            uint32_t bh[4][2], bl[4][2];
            #pragma unroll
            for (int nt = 0; nt < 4; nt++) {
                int nrow = wn + nt * 8 + g;
                const char* ph = bufB + nrow * ROWB3 + kb + t * 4;
                const char* pl = bufC + nrow * ROWB3 + kb + t * 4;
                bh[nt][0] = *(const uint32_t*)(ph);
                bh[nt][1] = *(const uint32_t*)(ph + 16);
                bl[nt][0] = *(const uint32_t*)(pl);
                bl[nt][1] = *(const uint32_t*)(pl + 16);
            }
            #pragma unroll
            for (int mt = 0; mt < 4; mt++) {
                int mrow = wm + mt * 16 + g;
                const char* ph = bufA + mrow * ROWB3 + kb + t * 4;
                const char* pl = bufL + mrow * ROWB3 + kb + t * 4;
                uint32_t ah0 = *(const uint32_t*)(ph);
                uint32_t ah1 = *(const uint32_t*)(ph + 8 * ROWB3);
                uint32_t ah2 = *(const uint32_t*)(ph + 16);
                uint32_t ah3 = *(const uint32_t*)(ph + 8 * ROWB3 + 16);
                uint32_t al0 = *(const uint32_t*)(pl);
                uint32_t al1 = *(const uint32_t*)(pl + 8 * ROWB3);
                uint32_t al2 = *(const uint32_t*)(pl + 16);
                uint32_t al3 = *(const uint32_t*)(pl + 8 * ROWB3 + 16);
                #pragma unroll
                for (int nt = 0; nt < 4; nt++) {
                    mma_bf16(acc[mt][nt], ah0, ah1, ah2, ah3, bh[nt][0], bh[nt][1]);
                    mma_bf16(acc[mt][nt], ah0, ah1, ah2, ah3, bl[nt][0], bl[nt][1]);
                    mma_bf16(acc[mt][nt], al0, al1, al2, al3, bh[nt][0], bh[nt][1]);
                }
            }
        }
        __syncthreads();
    }

    #pragma unroll
    for (int mt = 0; mt < 4; mt++) {
        int row = r0 + wm + mt * 16 + g;
        #pragma unroll
        for (int nt = 0; nt < 4; nt++) {
            int col = wn + nt * 8 + t * 2;
            if (row < NN) {
                __half2 p = __floats2half2_rn(acc[mt][nt][0], acc[mt][nt][1]);
                *(uint32_t*)((char*)g_xwh + ((size_t)row * DH + col) * 2) =
                    *(uint32_t*)&p;
            }
            if (row + 8 < NN) {
                __half2 p = __floats2half2_rn(acc[mt][nt][2], acc[mt][nt][3]);
                *(uint32_t*)((char*)g_xwh + ((size_t)(row + 8) * DH + col) * 2) =
                    *(uint32_t*)&p;
            }
        }
    }
}

#define GGEMM 391   // ceil(NN / 128)

__global__ __launch_bounds__(256, 2) void k_gemm_scan() {
    extern __shared__ char sm[];
    if (blockIdx.x < GGEMM) gemm_body(0, blockIdx.x, sm);
    else                    scan_body();
}

__global__ __launch_bounds__(256, 2) void k_gemm_mma(int layer) {
    extern __shared__ char sm[];
    gemm_body(layer, blockIdx.x, sm);
}

// ---------------- scatter ------------------------------------------------
__global__ void k_scatter() {
    int e = blockIdx.x * blockDim.x + threadIdx.x;
    if (e >= EE) return;
    int s = g_src[e];
    int d = g_dst[e];
    int p = g_off[d] + atomicAdd(&g_pos[d], 1);
    g_edge[p] = make_int2(s, __float_as_int(g_dinv[s] * g_dinv[d]));
}

// ---------------- aggregation --------------------------------------------
// one warp per node, lane handles 4 cols (uint2, 8B). Main loop: 4 edges
// per iteration via 2 int4 loads (16B-aligned after peel), two independent
// accumulator chains, no guards. Tail handled separately.
__device__ __forceinline__ void agg_edge(float4& acc, int2 e, const uint2* xw,
                                         int lane) {
    uint2 r = xw[(size_t)e.x * 32 + lane];
    float n = __int_as_float(e.y);
    float2 p01 = __half22float2(*(__half2*)&r.x);
    float2 p23 = __half22float2(*(__half2*)&r.y);
    acc.x += p01.x * n;
    acc.y += p01.y * n;
    acc.z += p23.x * n;
    acc.w += p23.y * n;
}

__global__ __launch_bounds__(256) void k_agg(const float* __restrict__ b,
                                             const float* __restrict__ Wfc,
                                             const float* __restrict__ bfc,
                                             float* __restrict__ out) {
    int warp = (blockIdx.x * blockDim.x + threadIdx.x) >> 5;
    int lane = threadIdx.x & 31;
    if (warp >= NN) return;
    int node = warp;

    const uint2* xw = (const uint2*)g_xwh;

    float dv   = g_dinv[node];
    float self = dv * dv;

    uint2 sraw = xw[node * 32 + lane];
    float2 f01 = __half22float2(*(__half2*)&sraw.x);
    float2 f23 = __half22float2(*(__half2*)&sraw.y);
    float4 accA = make_float4(f01.x * self, f01.y * self,
                              f23.x * self, f23.y * self);
    float4 accB = make_float4(0.f, 0.f, 0.f, 0.f);

    int start = g_off[node];
    int m     = g_cnt[node];
    int j = 0;

    // peel to 16B alignment of g_edge + start
    if ((start & 1) && m > 0) {
        agg_edge(accA, g_edge[start], xw, lane);
        j = 1;
    }

    // main: 4 edges per iteration, unguarded
    const int4* ep = (const int4*)(g_edge + start + j);
    int quads = (m - j) >> 2;
    for (int q = 0; q < quads; q++) {
        int4 ea = ep[2 * q];       // edges 0,1
        int4 eb = ep[2 * q + 1];   // edges 2,3
        uint2 r0 = xw[(size_t)ea.x * 32 + lane];
        uint2 r1 = xw[(size_t)ea.z * 32 + lane];
        uint2 r2 = xw[(size_t)eb.x * 32 + lane];
        uint2 r3 = xw[(size_t)eb.z * 32 + lane];
        float n0 = __int_as_float(ea.y);
        float n1 = __int_as_float(ea.w);
        float n2 = __int_as_float(eb.y);
        float n3 = __int_as_float(eb.w);
        float2 a01 = __half22float2(*(__half2*)&r0.x);
        float2 a23 = __half22float2(*(__half2*)&r0.y);
        float2 b01 = __half22float2(*(__half2*)&r1.x);
        float2 b23 = __half22float2(*(__half2*)&r1.y);
        float2 c01 = __half22float2(*(__half2*)&r2.x);
        float2 c23 = __half22float2(*(__half2*)&r2.y);
        float2 d01 = __half22float2(*(__half2*)&r3.x);
        float2 d23 = __half22float2(*(__half2*)&r3.y);
        // chain A: edges 0,2 ; chain B: edges 1,3
        accA.x += a01.x * n0; accB.x += b01.x * n1;
        accA.y += a01.y * n0; accB.y += b01.y * n1;
        accA.z += a23.x * n0; accB.z += b23.x * n1;
        accA.w += a23.y * n0; accB.w += b23.y * n1;
        accA.x += c01.x * n2; accB.x += d01.x * n3;
        accA.y += c01.y * n2; accB.y += d01.y * n3;
        accA.z += c23.x * n2; accB.z += d23.x * n3;
        accA.w += c23.y * n2; accB.w += d23.y * n3;
    }
    j += quads << 2;

    // tail
    for (; j < m; j++)
        agg_edge(accA, g_edge[start + j], xw, lane);

    float4 acc;
    acc.x = accA.x + accB.x;
    acc.y = accA.y + accB.y;
    acc.z = accA.z + accB.z;
    acc.w = accA.w + accB.w;

    float4 bb = ((const float4*)b)[lane];
    acc.x = fmaxf(acc.x + bb.x, 0.0f);
    acc.y = fmaxf(acc.y + bb.y, 0.0f);
    acc.z = fmaxf(acc.z + bb.z, 0.0f);
    acc.w = fmaxf(acc.w + bb.w, 0.0f);

    if (Wfc) {
        float4 w = ((const float4*)Wfc)[lane];
        float sum = acc.x * w.x + acc.y * w.y + acc.z * w.z + acc.w * w.w;
        #pragma unroll
        for (int d = 16; d > 0; d >>= 1)
            sum += __shfl_xor_sync(0xFFFFFFFFu, sum, d);
        if (lane == 0) out[node] = sum + bfc[0];
    } else {
        float rx, ry, rz, rw, z;
        uint32_t hx = bsplit_hi(acc.x, rx), hy = bsplit_hi(acc.y, ry);
        uint32_t hz = bsplit_hi(acc.z, rz), hw = bsplit_hi(acc.w, rw);
        uint32_t lx = bsplit_hi(rx, z), ly = bsplit_hi(ry, z);
        uint32_t lz = bsplit_hi(rz, z), lw = bsplit_hi(rw, z);
        ((uint2*)g_ah)[node * 32 + lane] =
            make_uint2(hx | (hy << 16), hz | (hw << 16));
        ((uint2*)g_al)[node * 32 + lane] =
            make_uint2(lx | (ly << 16), lz | (lw << 16));
    }
}

// ---------------- cleanup: restore zero invariant ------------------------
__global__ void k_cleanup() {
    int i = blockIdx.x * blockDim.x + threadIdx.x;
    if (i < NN) { g_cnt[i] = 0; g_pos[i] = 0; }
}

// ---------------- launch -------------------------------------------------
extern "C" void kernel_launch(void* const* d_in, const int* in_sizes, int n_in,
                              void* d_out, int out_size) {
    const float* x    = (const float*)d_in[0];
    const void*  ei   = d_in[1];
    const float* W1   = (const float*)d_in[2];
    const float* b1   = (const float*)d_in[3];
    const float* W2   = (const float*)d_in[4];
    const float* b2   = (const float*)d_in[5];
    const float* W3   = (const float*)d_in[6];
    const float* b3   = (const float*)d_in[7];
    const float* Wfc  = (const float*)d_in[8];
    const float* bfc  = (const float*)d_in[9];
    float* out = (float*)d_out;

    static int smem_set = 0;
    if (!smem_set) {
        cudaFuncSetAttribute(k_gemm_scan,
                             cudaFuncAttributeMaxDynamicSharedMemorySize,
                             SM3_TOTAL);
        cudaFuncSetAttribute(k_gemm_mma,
                             cudaFuncAttributeMaxDynamicSharedMemorySize,
                             SM3_TOTAL);
        smem_set = 1;
    }

    const int TB = 256;
    int ge = (EE + TB - 1) / TB;
    int gn = (NN + TB - 1) / TB;
    int gwarp = (NN * 32 + TB - 1) / TB;

    k_prep<<<GSX + GW + GE, TB>>>(x, W1, W2, W3, ei);          // 1
    k_gemm_scan<<<GGEMM + 1, 256, SM3_TOTAL>>>();              // 2
    k_scatter<<<ge, TB>>>();                                   // 3
    k_agg<<<gwarp, TB>>>(b1, nullptr, nullptr, nullptr);       // 4 <- profiled
    k_gemm_mma<<<GGEMM, 256, SM3_TOTAL>>>(1);                  // 5
    k_agg<<<gwarp, TB>>>(b2, nullptr, nullptr, nullptr);       // 6
    k_gemm_mma<<<GGEMM, 256, SM3_TOTAL>>>(2);                  // 7
    k_agg<<<gwarp, TB>>>(b3, Wfc, bfc, out);                   // 8
    k_cleanup<<<gn, TB>>>();                                   // 9
}